// round 4
// baseline (speedup 1.0000x reference)
#include <cuda_runtime.h>
#include <cuda_bf16.h>
#include <cstdint>

// ---------------------------------------------------------------------------
// transformer_75419625718098: talking-heads causal attention
// B=1, N=2048, C=1024, H=16, D=64
// Round 4: fused QK^T+premix+pos_bias (register head-mix, cp.async, no S0
// materialization); dedicated 64x64 PV gemm (2x CTA parallelism).
// ---------------------------------------------------------------------------

#define NTOK 2048
#define NHEAD 16
#define HDIM 64
#define CDIM 1024
#define NN (2048*2048)

// 128x64 gemm tiling (qkv, out-proj)
#define TM 128
#define TN 64
#define AS2 136
#define BS2 72
#define GEMM_SMEM ((2*16*AS2 + 2*16*BS2) * sizeof(uint2))   // 53248

// qk_mix smem layout (uint2 units): per buffer Q[64][66] + K[32][66]
#define QKS 66
#define QBUF (64*QKS)            // 4224
#define KBUF (32*QKS)            // 2112
#define QKBUF (QBUF+KBUF)        // 6336
#define QKMIX_SMEM (2*QKBUF*sizeof(uint2))   // 101376

// ------------------------- device scratch ----------------------------------
__device__ float g_qkv[2048 * 3072];
__device__ uint2 g_qn2[NHEAD * NTOK * HDIM];   // split-tf32 (hi,lo), temp folded
__device__ uint2 g_kn2[NHEAD * NTOK * HDIM];
__device__ float g_vT [NHEAD * HDIM * NTOK];
__device__ float g_bufA[(long long)NHEAD * NN]; // Pm
__device__ float g_bufB[(long long)NHEAD * NN]; // s (mixed logits)
__device__ float g_m   [NHEAD * NTOK];
__device__ float g_invl[NHEAD * NTOK];
__device__ float g_o2  [NTOK * CDIM];

// fast exp on the FMA pipe
__device__ __forceinline__ float fexp(float x) {
    float t = fmaxf(x * 1.4426950408889634f, -126.0f);
    int ei = __float2int_rd(t);
    float f = t - (float)ei;
    float y = 0.69314718055994531f * f;
    float p = fmaf(y, 1.3888889e-3f, 8.3333333e-3f);
    p = fmaf(y, p, 4.1666667e-2f);
    p = fmaf(y, p, 1.6666667e-1f);
    p = fmaf(y, p, 0.5f);
    p = fmaf(y, p, 1.0f);
    p = fmaf(y, p, 1.0f);
    return p * __int_as_float((ei + 127) << 23);
}

__device__ __forceinline__ uint32_t f2tf32(float x) {
    uint32_t r;
    asm("cvt.rna.tf32.f32 %0, %1;" : "=r"(r) : "f"(x));
    return r;
}
__device__ __forceinline__ uint2 split_tf32(float v) {
    uint32_t hi = f2tf32(v);
    uint32_t lo = f2tf32(v - __uint_as_float(hi));
    return make_uint2(hi, lo);
}
__device__ __forceinline__ void mma_tf32(float* c, const uint32_t* a, const uint32_t* b) {
    asm volatile(
        "mma.sync.aligned.m16n8k8.row.col.f32.tf32.tf32.f32 "
        "{%0,%1,%2,%3},{%4,%5,%6,%7},{%8,%9},{%0,%1,%2,%3};"
        : "+f"(c[0]), "+f"(c[1]), "+f"(c[2]), "+f"(c[3])
        : "r"(a[0]), "r"(a[1]), "r"(a[2]), "r"(a[3]), "r"(b[0]), "r"(b[1]));
}
__device__ __forceinline__ void cpa16(uint32_t dst, const void* src) {
    asm volatile("cp.async.cg.shared.global [%0], [%1], 16;" :: "r"(dst), "l"(src));
}

// ---------------- split-tf32 gemm (128x64): C = A * B^T ---------------------
__global__ void __launch_bounds__(256, 2)
gemm_tf32x2(const float* __restrict__ A, const float* __restrict__ B,
            float* __restrict__ C,
            int K, int lda, int ldb, int ldc)
{
    int j0 = blockIdx.x * TN;
    int i0 = blockIdx.y * TM;

    extern __shared__ uint2 smem_dyn[];
    uint2* As = smem_dyn;
    uint2* Bs = smem_dyn + 2 * 16 * AS2;

    int t    = threadIdx.x;
    int lane = t & 31;
    int wid  = t >> 5;
    int wm   = (wid & 3) * 32;
    int wn   = (wid >> 2) * 32;
    int gid  = lane >> 2;
    int tig  = lane & 3;

    int a_row = t >> 1;
    int a_k0  = (t & 1) * 8;
    int b_row = t >> 2;
    int b_k0  = (t & 3) * 4;

    const float* Ap = A + (long long)(i0 + a_row) * lda + a_k0;
    const float* Bp = B + (long long)(j0 + b_row) * ldb + b_k0;

    float acc[2][4][4];
#pragma unroll
    for (int mt = 0; mt < 2; mt++)
#pragma unroll
        for (int nt = 0; nt < 4; nt++)
#pragma unroll
            for (int e = 0; e < 4; e++) acc[mt][nt][e] = 0.0f;

    float4 ra0 = *(const float4*)(Ap);
    float4 ra1 = *(const float4*)(Ap + 4);
    float4 rb0 = *(const float4*)(Bp);

#define STAGE(buf)                                                           \
    do {                                                                     \
        uint2* Ab = As + (buf) * 16 * AS2;                                   \
        uint2* Bb = Bs + (buf) * 16 * BS2;                                   \
        Ab[(a_k0 + 0) * AS2 + a_row] = split_tf32(ra0.x);                    \
        Ab[(a_k0 + 1) * AS2 + a_row] = split_tf32(ra0.y);                    \
        Ab[(a_k0 + 2) * AS2 + a_row] = split_tf32(ra0.z);                    \
        Ab[(a_k0 + 3) * AS2 + a_row] = split_tf32(ra0.w);                    \
        Ab[(a_k0 + 4) * AS2 + a_row] = split_tf32(ra1.x);                    \
        Ab[(a_k0 + 5) * AS2 + a_row] = split_tf32(ra1.y);                    \
        Ab[(a_k0 + 6) * AS2 + a_row] = split_tf32(ra1.z);                    \
        Ab[(a_k0 + 7) * AS2 + a_row] = split_tf32(ra1.w);                    \
        Bb[(b_k0 + 0) * BS2 + b_row] = split_tf32(rb0.x);                    \
        Bb[(b_k0 + 1) * BS2 + b_row] = split_tf32(rb0.y);                    \
        Bb[(b_k0 + 2) * BS2 + b_row] = split_tf32(rb0.z);                    \
        Bb[(b_k0 + 3) * BS2 + b_row] = split_tf32(rb0.w);                    \
    } while (0)

    STAGE(0);
    __syncthreads();
    int cur = 0;

    for (int k0 = 0; k0 < K; k0 += 16) {
        bool nxt = (k0 + 16) < K;
        if (nxt) {
            ra0 = *(const float4*)(Ap + k0 + 16);
            ra1 = *(const float4*)(Ap + k0 + 20);
            rb0 = *(const float4*)(Bp + k0 + 16);
        }
        const uint2* Ab = As + cur * 16 * AS2;
        const uint2* Bb = Bs + cur * 16 * BS2;
#pragma unroll
        for (int k8 = 0; k8 < 16; k8 += 8) {
            uint2 a[2][4];
#pragma unroll
            for (int mt = 0; mt < 2; mt++) {
                int r0 = wm + mt * 16 + gid;
                a[mt][0] = Ab[(k8 + tig) * AS2 + r0];
                a[mt][1] = Ab[(k8 + tig) * AS2 + r0 + 8];
                a[mt][2] = Ab[(k8 + tig + 4) * AS2 + r0];
                a[mt][3] = Ab[(k8 + tig + 4) * AS2 + r0 + 8];
            }
            uint2 b[4][2];
#pragma unroll
            for (int nt = 0; nt < 4; nt++) {
                int c = wn + nt * 8 + gid;
                b[nt][0] = Bb[(k8 + tig) * BS2 + c];
                b[nt][1] = Bb[(k8 + tig + 4) * BS2 + c];
            }
#pragma unroll
            for (int mt = 0; mt < 2; mt++) {
                uint32_t ah[4] = {a[mt][0].x, a[mt][1].x, a[mt][2].x, a[mt][3].x};
                uint32_t al[4] = {a[mt][0].y, a[mt][1].y, a[mt][2].y, a[mt][3].y};
#pragma unroll
                for (int nt = 0; nt < 4; nt++) {
                    uint32_t bh[2] = {b[nt][0].x, b[nt][1].x};
                    uint32_t bl[2] = {b[nt][0].y, b[nt][1].y};
                    mma_tf32(acc[mt][nt], ah, bh);
                    mma_tf32(acc[mt][nt], al, bh);
                    mma_tf32(acc[mt][nt], ah, bl);
                }
            }
        }
        if (nxt) {
            STAGE(cur ^ 1);
            __syncthreads();
            cur ^= 1;
        }
    }
#undef STAGE

#pragma unroll
    for (int mt = 0; mt < 2; mt++) {
        int r = i0 + wm + mt * 16 + gid;
#pragma unroll
        for (int nt = 0; nt < 4; nt++) {
            int c = j0 + wn + nt * 8 + tig * 2;
            C[(long long)r * ldc + c]           = acc[mt][nt][0];
            C[(long long)r * ldc + c + 1]       = acc[mt][nt][1];
            C[(long long)(r + 8) * ldc + c]     = acc[mt][nt][2];
            C[(long long)(r + 8) * ldc + c + 1] = acc[mt][nt][3];
        }
    }
}

// ------------------- qkv split + l2norm + presplit + kv output --------------
__global__ void qkv_split_kernel(const float* __restrict__ qkv,
                                 const float* __restrict__ tptr,
                                 uint2* __restrict__ qn2, uint2* __restrict__ kn2,
                                 float* __restrict__ vT, float* __restrict__ kv_out)
{
    int n = blockIdx.x, h = blockIdx.y, d = threadIdx.x; // 64 threads
    const float* base = qkv + (long long)n * 3072 + h * 192 + d * 3;
    float q = base[0], k = base[1], v = base[2];

    float sq = q * q, sk = k * k;
#pragma unroll
    for (int o = 16; o; o >>= 1) {
        sq += __shfl_down_sync(0xffffffffu, sq, o);
        sk += __shfl_down_sync(0xffffffffu, sk, o);
    }
    __shared__ float sh[4];
    int lane = d & 31, w = d >> 5;
    if (lane == 0) { sh[w] = sq; sh[2 + w] = sk; }
    __syncthreads();
    float nq = sqrtf(sh[0] + sh[1]);
    float nk = sqrtf(sh[2] + sh[3]);
    float temp = tptr[0];

    int idx = (h * NTOK + n) * HDIM + d;
    qn2[idx] = split_tf32(q / fmaxf(nq, 1e-12f) * temp);
    kn2[idx] = split_tf32(k / fmaxf(nk, 1e-12f));
    vT[(h * HDIM + d) * NTOK + n] = v;
    kv_out[idx] = k;
    kv_out[NHEAD * NTOK * HDIM + idx] = v;
}

// ------- fused QK^T (16 heads) + talking-heads pre mix + pos_bias -----------
// CTA: 64 (i) x 32 (j) tile, all heads. S kept in registers (frag mapping is
// head-invariant), head-mix done in registers, writes s only.
__global__ void __launch_bounds__(256, 1)
qk_mix_kernel(const uint2* __restrict__ qn2, const uint2* __restrict__ kn2,
              const float* __restrict__ Wpre, const float* __restrict__ bpre,
              const float* __restrict__ pb, float* __restrict__ s)
{
    int j0 = blockIdx.x * 32;
    int i0 = blockIdx.y * 64;
    if (j0 > i0 + 63) return;

    extern __shared__ uint2 sm[];
    uint32_t smbase = (uint32_t)__cvta_generic_to_shared(sm);

    __shared__ float w[16][16];
    __shared__ float bp[16];

    int t    = threadIdx.x;
    int lane = t & 31;
    int wid  = t >> 5;
    int wm   = (wid & 3) * 16;      // 4 m-tiles of 16
    int wn   = (wid >> 2) * 16;     // 2 n-tiles of 16
    int gid  = lane >> 2;
    int tig  = lane & 3;

    w[t >> 4][t & 15] = Wpre[t];
    if (t < 16) bp[t] = bpre[t];

    // cp.async staging maps
    int qrow = t & 63, qkb = (t >> 6) * 16;   // 8x16B per thread
    int kcol = t & 31, kkb = (t >> 5) * 8;    // 4x16B per thread

    const uint2* qbase = qn2 + (long long)(i0 + qrow) * 64 + qkb;
    const uint2* kbase = kn2 + (long long)(j0 + kcol) * 64 + kkb;

#define ISSUE(h, buf)                                                          \
    do {                                                                       \
        const uint2* qp = qbase + (long long)(h) * (NTOK * 64);                \
        const uint2* kp = kbase + (long long)(h) * (NTOK * 64);                \
        uint32_t qd = smbase + ((buf) * QKBUF + qrow * QKS + qkb) * 8;         \
        uint32_t kd = smbase + ((buf) * QKBUF + QBUF + kcol * QKS + kkb) * 8;  \
        _Pragma("unroll")                                                      \
        for (int u = 0; u < 8; u++) cpa16(qd + u * 16, qp + 2 * u);            \
        _Pragma("unroll")                                                      \
        for (int u = 0; u < 4; u++) cpa16(kd + u * 16, kp + 2 * u);            \
        asm volatile("cp.async.commit_group;");                                \
    } while (0)

    float accS[16][2][4];
#pragma unroll
    for (int h = 0; h < 16; h++)
#pragma unroll
        for (int nt = 0; nt < 2; nt++)
#pragma unroll
            for (int e = 0; e < 4; e++) accS[h][nt][e] = 0.0f;

    ISSUE(0, 0);

#pragma unroll
    for (int h = 0; h < 16; h++) {
        __syncthreads();                    // prior buffer fully consumed
        if (h < 15) ISSUE(h + 1, (h + 1) & 1);
        if (h < 15) asm volatile("cp.async.wait_group 1;");
        else        asm volatile("cp.async.wait_group 0;");
        __syncthreads();                    // current buffer visible to all

        const uint2* Q = sm + (h & 1) * QKBUF;
        const uint2* Kb = Q + QBUF;
        int r0 = wm + gid;
#pragma unroll
        for (int k8 = 0; k8 < 64; k8 += 8) {
            uint2 a0 = Q[r0 * QKS + k8 + tig];
            uint2 a1 = Q[(r0 + 8) * QKS + k8 + tig];
            uint2 a2 = Q[r0 * QKS + k8 + tig + 4];
            uint2 a3 = Q[(r0 + 8) * QKS + k8 + tig + 4];
            uint32_t ah[4] = {a0.x, a1.x, a2.x, a3.x};
            uint32_t al[4] = {a0.y, a1.y, a2.y, a3.y};
#pragma unroll
            for (int nt = 0; nt < 2; nt++) {
                int c = wn + nt * 8 + gid;
                uint2 b0 = Kb[c * QKS + k8 + tig];
                uint2 b1 = Kb[c * QKS + k8 + tig + 4];
                uint32_t bh[2] = {b0.x, b1.x};
                uint32_t bl[2] = {b0.y, b1.y};
                mma_tf32(accS[h][nt], ah, bh);
                mma_tf32(accS[h][nt], al, bh);
                mma_tf32(accS[h][nt], ah, bl);
            }
        }
    }
#undef ISSUE

    // head mix in registers + pos_bias, write s
#pragma unroll
    for (int nt = 0; nt < 2; nt++) {
#pragma unroll
        for (int eh = 0; eh < 2; eh++) {
            int r = i0 + wm + gid + eh * 8;
            int c = j0 + wn + nt * 8 + tig * 2;
            if (c > r) continue;
            bool c1ok = (c + 1 <= r);
            long long cell = (long long)r * NTOK + c;
#pragma unroll
            for (int g = 0; g < 16; g++) {
                float a0 = bp[g], a1 = bp[g];
#pragma unroll
                for (int h = 0; h < 16; h++) {
                    float wgh = w[g][h];
                    a0 = fmaf(wgh, accS[h][nt][eh * 2 + 0], a0);
                    a1 = fmaf(wgh, accS[h][nt][eh * 2 + 1], a1);
                }
                const float* pbp = pb + (long long)g * NN + cell;
                float* sp = s + (long long)g * NN + cell;
                if (c1ok) {
                    float2 pbv = *(const float2*)pbp;
                    float2 o = make_float2(a0 + pbv.x, a1 + pbv.y);
                    *(float2*)sp = o;
                } else {
                    sp[0] = a0 + pbp[0];
                }
            }
        }
    }
}

// ---------------- per-row softmax stats (causal): m, 1/l --------------------
__global__ void rowstats_kernel(const float* __restrict__ s,
                                float* __restrict__ m_out, float* __restrict__ invl_out)
{
    int i = blockIdx.x, g = blockIdx.y;
    int len = i + 1;
    const float* row = s + (long long)g * NN + (long long)i * NTOK;
    __shared__ float red[256];
    int t = threadIdx.x;

    float mx = -3.4e38f;
    for (int j = t; j < len; j += 256) mx = fmaxf(mx, row[j]);
    red[t] = mx; __syncthreads();
    for (int o = 128; o; o >>= 1) {
        if (t < o) red[t] = fmaxf(red[t], red[t + o]);
        __syncthreads();
    }
    float m = red[0];
    __syncthreads();

    float sum = 0.0f;
    for (int j = t; j < len; j += 256) sum += fexp(row[j] - m);
    red[t] = sum; __syncthreads();
    for (int o = 128; o; o >>= 1) {
        if (t < o) red[t] += red[t + o];
        __syncthreads();
    }
    if (t == 0) {
        m_out[g * NTOK + i] = m;
        invl_out[g * NTOK + i] = 1.0f / red[0];
    }
}

// -------- softmax + talking-heads post: Pm = Wpost @ (exp(s-m)/l) + bpost ---
__global__ void softmax_mix_kernel(const float* __restrict__ s,
                                   const float* __restrict__ m_arr,
                                   const float* __restrict__ invl_arr,
                                   const float* __restrict__ Wpost,
                                   const float* __restrict__ bpost,
                                   float* __restrict__ Pm)
{
    int j0 = blockIdx.x * 64, i0 = blockIdx.y * 64;
    if (j0 > i0 + 63) return;
    __shared__ float w[16][16];
    __shared__ float bp[16];
    __shared__ float sm[16][64];
    __shared__ float sil[16][64];
    int t = threadIdx.x;
    w[t >> 4][t & 15] = Wpost[t];
    if (t < 16) bp[t] = bpost[t];
#pragma unroll
    for (int e = 0; e < 4; e++) {
        int id = t + e * 256;
        int h = id >> 6, ir = id & 63;
        sm[h][ir]  = m_arr[h * NTOK + i0 + ir];
        sil[h][ir] = invl_arr[h * NTOK + i0 + ir];
    }
    __syncthreads();

    int tj = t & 63, ti = t >> 6;
    for (int r = 0; r < 16; r++) {
        int ir = (r << 2) + ti;
        int i = i0 + ir;
        int j = j0 + tj;
        long long cell = (long long)i * NTOK + j;
        if (j > i) {
#pragma unroll
            for (int g = 0; g < 16; g++) Pm[(long long)g * NN + cell] = 0.0f;
            continue;
        }
        float acc[16];
#pragma unroll
        for (int g = 0; g < 16; g++) acc[g] = bp[g];
#pragma unroll
        for (int h = 0; h < 16; h++) {
            float e = fexp(__ldg(s + (long long)h * NN + cell) - sm[h][ir]) * sil[h][ir];
#pragma unroll
            for (int g = 0; g < 16; g++) acc[g] = fmaf(w[g][h], e, acc[g]);
        }
#pragma unroll
        for (int g = 0; g < 16; g++) Pm[(long long)g * NN + cell] = acc[g];
    }
}

// ---------------- PV gemm (64x64 tiles, split-tf32): o2 = Pm @ v ------------
__global__ void __launch_bounds__(256, 2)
gemm64_pv(const float* __restrict__ Pm, const float* __restrict__ vT,
          float* __restrict__ o2)
{
    int i0 = blockIdx.y * 64;
    int g  = blockIdx.z;
    const float* A = Pm + (long long)g * NN;            // [2048][2048]
    const float* B = vT + (long long)g * HDIM * NTOK;   // [64][2048]
    float* C = o2 + g * 64;                             // ldc 1024
    int Keff = i0 + 64;

    __shared__ uint2 As[2 * 16 * 72];
    __shared__ uint2 Bs[2 * 16 * 72];

    int t    = threadIdx.x;
    int lane = t & 31;
    int wid  = t >> 5;
    int wm   = (wid & 1) * 32;
    int wn   = (wid >> 1) * 16;
    int gid  = lane >> 2;
    int tig  = lane & 3;

    int a_row = t >> 2;            // 0..63
    int a_k0  = (t & 3) * 4;

    const float* Ap = A + (long long)(i0 + a_row) * NTOK + a_k0;
    const float* Bp = B + (long long)a_row * NTOK + a_k0;

    float acc[2][2][4];
#pragma unroll
    for (int mt = 0; mt < 2; mt++)
#pragma unroll
        for (int nt = 0; nt < 2; nt++)
#pragma unroll
            for (int e = 0; e < 4; e++) acc[mt][nt][e] = 0.0f;

    float4 ra = *(const float4*)(Ap);
    float4 rb = *(const float4*)(Bp);

#define STAGE64(buf)                                                          \
    do {                                                                      \
        uint2* Ab = As + (buf) * 16 * 72;                                     \
        uint2* Bb = Bs + (buf) * 16 * 72;                                     \
        Ab[(a_k0 + 0) * 72 + a_row] = split_tf32(ra.x);                       \
        Ab[(a_k0 + 1) * 72 + a_row] = split_tf32(ra.y);                       \
        Ab[(a_k0 + 2) * 72 + a_row] = split_tf32(ra.z);                       \
        Ab[(a_k0 + 3) * 72 + a_row] = split_tf32(ra.w);                       \
        Bb[(a_k0 + 0) * 72 + a_row] = split_tf32(rb.x);                       \
        Bb[(a_k0 + 1) * 72 + a_row] = split_tf32(rb.y);                       \
        Bb[(a_k0 + 2) * 72 + a_row] = split_tf32(rb.z);                       \
        Bb[(a_k0 + 3) * 72 + a_row] = split_tf32(rb.w);                       \
    } while (0)

    STAGE64(0);
    __syncthreads();
    int cur = 0;

    for (int k0 = 0; k0 < Keff; k0 += 16) {
        bool nxt = (k0 + 16) < Keff;
        if (nxt) {
            ra = *(const float4*)(Ap + k0 + 16);
            rb = *(const float4*)(Bp + k0 + 16);
        }
        const uint2* Ab = As + cur * 16 * 72;
        const uint2* Bb = Bs + cur * 16 * 72;
#pragma unroll
        for (int k8 = 0; k8 < 16; k8 += 8) {
            uint2 a[2][4];
#pragma unroll
            for (int mt = 0; mt < 2; mt++) {
                int r0 = wm + mt * 16 + gid;
                a[mt][0] = Ab[(k8 + tig) * 72 + r0];
                a[mt][1] = Ab[(k8 + tig) * 72 + r0 + 8];
                a[mt][2] = Ab[(k8 + tig + 4) * 72 + r0];
                a[mt][3] = Ab[(k8 + tig + 4) * 72 + r0 + 8];
            }
            uint2 b[2][2];
#pragma unroll
            for (int nt = 0; nt < 2; nt++) {
                int c = wn + nt * 8 + gid;
                b[nt][0] = Bb[(k8 + tig) * 72 + c];
                b[nt][1] = Bb[(k8 + tig + 4) * 72 + c];
            }
#pragma unroll
            for (int mt = 0; mt < 2; mt++) {
                uint32_t ah[4] = {a[mt][0].x, a[mt][1].x, a[mt][2].x, a[mt][3].x};
                uint32_t al[4] = {a[mt][0].y, a[mt][1].y, a[mt][2].y, a[mt][3].y};
#pragma unroll
                for (int nt = 0; nt < 2; nt++) {
                    uint32_t bh[2] = {b[nt][0].x, b[nt][1].x};
                    uint32_t bl[2] = {b[nt][0].y, b[nt][1].y};
                    mma_tf32(acc[mt][nt], ah, bh);
                    mma_tf32(acc[mt][nt], al, bh);
                    mma_tf32(acc[mt][nt], ah, bl);
                }
            }
        }
        if (nxt) {
            STAGE64(cur ^ 1);
            __syncthreads();
            cur ^= 1;
        }
    }
#undef STAGE64

#pragma unroll
    for (int mt = 0; mt < 2; mt++) {
        int r = i0 + wm + mt * 16 + gid;
#pragma unroll
        for (int nt = 0; nt < 2; nt++) {
            int c = wn + nt * 8 + tig * 2;
            C[(long long)r * CDIM + c]           = acc[mt][nt][0];
            C[(long long)r * CDIM + c + 1]       = acc[mt][nt][1];
            C[(long long)(r + 8) * CDIM + c]     = acc[mt][nt][2];
            C[(long long)(r + 8) * CDIM + c + 1] = acc[mt][nt][3];
        }
    }
}

// ---------------------------------------------------------------------------
extern "C" void kernel_launch(void* const* d_in, const int* in_sizes, int n_in,
                              void* d_out, int out_size)
{
    const float* x     = (const float*)d_in[0];
    const float* pb    = (const float*)d_in[1];
    const float* Wqkv  = (const float*)d_in[3];
    const float* Wout  = (const float*)d_in[4];
    const float* temp  = (const float*)d_in[5];
    const float* Wpre  = (const float*)d_in[6];
    const float* bpre  = (const float*)d_in[7];
    const float* Wpost = (const float*)d_in[8];
    const float* bpost = (const float*)d_in[9];
    float* out = (float*)d_out;
    float* kv_out = out + NTOK * CDIM;

    float *qkv_p, *vT_p, *bufA_p, *bufB_p, *m_p, *invl_p, *o2_p;
    uint2 *qn2_p, *kn2_p;
    cudaGetSymbolAddress((void**)&qkv_p, g_qkv);
    cudaGetSymbolAddress((void**)&qn2_p, g_qn2);
    cudaGetSymbolAddress((void**)&kn2_p, g_kn2);
    cudaGetSymbolAddress((void**)&vT_p, g_vT);
    cudaGetSymbolAddress((void**)&bufA_p, g_bufA);
    cudaGetSymbolAddress((void**)&bufB_p, g_bufB);
    cudaGetSymbolAddress((void**)&m_p, g_m);
    cudaGetSymbolAddress((void**)&invl_p, g_invl);
    cudaGetSymbolAddress((void**)&o2_p, g_o2);

    cudaFuncSetAttribute(gemm_tf32x2, cudaFuncAttributeMaxDynamicSharedMemorySize,
                         (int)GEMM_SMEM);
    cudaFuncSetAttribute(qk_mix_kernel, cudaFuncAttributeMaxDynamicSharedMemorySize,
                         (int)QKMIX_SMEM);

    // 1) qkv = x @ Wqkv^T : [2048,3072]
    gemm_tf32x2<<<dim3(3072 / TN, 2048 / TM, 1), 256, GEMM_SMEM>>>(
        x, Wqkv, qkv_p, 1024, 1024, 1024, 3072);

    // 2) split + l2norm (+temperature) + presplit tf32 pairs + kv output + vT
    qkv_split_kernel<<<dim3(NTOK, NHEAD), 64>>>(qkv_p, temp, qn2_p, kn2_p, vT_p, kv_out);

    // 3) fused QK^T (all heads) + pre-mix + pos_bias -> s
    qk_mix_kernel<<<dim3(64, 32), 256, QKMIX_SMEM>>>(
        qn2_p, kn2_p, Wpre, bpre, pb, bufB_p);

    // 4) per-row max / inv-sum-exp
    rowstats_kernel<<<dim3(NTOK, NHEAD), 256>>>(bufB_p, m_p, invl_p);

    // 5) softmax + post talking-heads mix -> Pm
    softmax_mix_kernel<<<dim3(32, 32), 256>>>(bufB_p, m_p, invl_p, Wpost, bpost, bufA_p);

    // 6) o2 = Pm @ v (causal K), 64x64 tiles, 512 CTAs
    gemm64_pv<<<dim3(1, 32, NHEAD), 256>>>(bufA_p, vT_p, o2_p);

    // 7) out = o2 @ Wout^T
    gemm_tf32x2<<<dim3(1024 / TN, 2048 / TM, 1), 256, GEMM_SMEM>>>(
        o2_p, Wout, out, 1024, 1024, 1024, 1024);
}

// round 5
// speedup vs baseline: 1.6062x; 1.6062x over previous
#include <cuda_runtime.h>
#include <cuda_bf16.h>
#include <cstdint>

// ---------------------------------------------------------------------------
// transformer_75419625718098: talking-heads causal attention
// B=1, N=2048, C=1024, H=16, D=64
// Round 5: R3 topology, GEMMs on split-bf16 m16n8k16 (half the MMA instr,
// half the fragment LDS, half the staging stores of tf32x2); single-pass
// rowstats; occupancy fix on softmax_mix.
// ---------------------------------------------------------------------------

#define NTOK 2048
#define NHEAD 16
#define HDIM 64
#define CDIM 1024
#define NN (2048*2048)

// GEMM tiling: CTA 128x64, k-step 16, kpairs (2 elems) per uint2
#define TM 128
#define TN 64
#define AS2 136   // uint2 stride per kpair row (A): 128 + 8
#define BS2 72    // uint2 stride per kpair row (B): 64 + 8
#define GEMM_SMEM ((2*8*AS2 + 2*8*BS2) * sizeof(uint2))   // 26624 bytes

// ------------------------- device scratch ----------------------------------
__device__ float g_qkv[2048 * 3072];
__device__ float g_qn [NHEAD * NTOK * HDIM];
__device__ float g_kn [NHEAD * NTOK * HDIM];
__device__ float g_vT [NHEAD * HDIM * NTOK];
__device__ float g_bufA[(long long)NHEAD * NN]; // S0, then Pm
__device__ float g_bufB[(long long)NHEAD * NN]; // s (mixed logits)
__device__ float g_m   [NHEAD * NTOK];
__device__ float g_invl[NHEAD * NTOK];
__device__ float g_o2  [NTOK * CDIM];

// fast exp on the FMA pipe
__device__ __forceinline__ float fexp(float x) {
    float t = fmaxf(x * 1.4426950408889634f, -126.0f);
    int ei = __float2int_rd(t);
    float f = t - (float)ei;
    float y = 0.69314718055994531f * f;
    float p = fmaf(y, 1.3888889e-3f, 8.3333333e-3f);
    p = fmaf(y, p, 4.1666667e-2f);
    p = fmaf(y, p, 1.6666667e-1f);
    p = fmaf(y, p, 0.5f);
    p = fmaf(y, p, 1.0f);
    p = fmaf(y, p, 1.0f);
    return p * __int_as_float((ei + 127) << 23);
}

// pack two consecutive-k elements as (hi_bf16x2, lo_bf16x2)
__device__ __forceinline__ uint2 pack2_bf16(float x0, float x1) {
    unsigned short h0 = __bfloat16_as_ushort(__float2bfloat16(x0));
    unsigned short h1 = __bfloat16_as_ushort(__float2bfloat16(x1));
    float r0 = x0 - __bfloat162float(__ushort_as_bfloat16(h0));
    float r1 = x1 - __bfloat162float(__ushort_as_bfloat16(h1));
    unsigned short l0 = __bfloat16_as_ushort(__float2bfloat16(r0));
    unsigned short l1 = __bfloat16_as_ushort(__float2bfloat16(r1));
    return make_uint2((uint32_t)h0 | ((uint32_t)h1 << 16),
                      (uint32_t)l0 | ((uint32_t)l1 << 16));
}

__device__ __forceinline__ void mma_bf16(float* c, const uint32_t* a, const uint32_t* b) {
    asm volatile(
        "mma.sync.aligned.m16n8k16.row.col.f32.bf16.bf16.f32 "
        "{%0,%1,%2,%3},{%4,%5,%6,%7},{%8,%9},{%0,%1,%2,%3};"
        : "+f"(c[0]), "+f"(c[1]), "+f"(c[2]), "+f"(c[3])
        : "r"(a[0]), "r"(a[1]), "r"(a[2]), "r"(a[3]), "r"(b[0]), "r"(b[1]));
}

// ---------------- split-bf16 gemm (128x64): C = A * B^T ---------------------
// A[M][K] (lda), B[N][K] (ldb), C[M][N] (ldc). 256 threads, 8 warps (4m x 2n,
// 32x32 warp tiles). k-step 16. 3 MMAs (hh, lh, hl) per fragment pair.
__global__ void __launch_bounds__(256, 2)
gemm_bf16x2(const float* __restrict__ A, const float* __restrict__ B,
            float* __restrict__ C,
            int K, int lda, int ldb, int ldc,
            long long sA, long long sB, long long sC,
            int causal_skip, int causal_klimit)
{
    int j0 = blockIdx.x * TN;
    int i0 = blockIdx.y * TM;
    if (causal_skip && j0 > i0 + TM - 1) return;
    int bz = blockIdx.z;
    A += (long long)bz * sA;
    B += (long long)bz * sB;
    C += (long long)bz * sC;
    int Keff = causal_klimit ? min(K, i0 + TM) : K;

    extern __shared__ uint2 smem_dyn[];
    uint2* As = smem_dyn;               // [2][8][AS2]
    uint2* Bs = smem_dyn + 2 * 8 * AS2; // [2][8][BS2]

    int t    = threadIdx.x;
    int lane = t & 31;
    int wid  = t >> 5;
    int wm   = (wid & 3) * 32;
    int wn   = (wid >> 2) * 32;
    int gid  = lane >> 2;
    int tig  = lane & 3;

    // staging maps
    int a_row = t >> 1;            // 0..127
    int a_kp0 = (t & 1) * 4;       // kpair offset: 0 or 4 (each covers 8 floats)
    int b_row = t >> 2;            // 0..63
    int b_kp0 = (t & 3) * 2;       // kpair offset: 0,2,4,6 (each covers 4 floats)

    const float* Ap = A + (long long)(i0 + a_row) * lda + a_kp0 * 2;
    const float* Bp = B + (long long)(j0 + b_row) * ldb + b_kp0 * 2;

    float acc[2][4][4];
#pragma unroll
    for (int mt = 0; mt < 2; mt++)
#pragma unroll
        for (int nt = 0; nt < 4; nt++)
#pragma unroll
            for (int e = 0; e < 4; e++) acc[mt][nt][e] = 0.0f;

    float4 ra0 = *(const float4*)(Ap);
    float4 ra1 = *(const float4*)(Ap + 4);
    float4 rb0 = *(const float4*)(Bp);

#define STAGE(buf)                                                           \
    do {                                                                     \
        uint2* Ab = As + (buf) * 8 * AS2;                                    \
        uint2* Bb = Bs + (buf) * 8 * BS2;                                    \
        Ab[(a_kp0 + 0) * AS2 + a_row] = pack2_bf16(ra0.x, ra0.y);            \
        Ab[(a_kp0 + 1) * AS2 + a_row] = pack2_bf16(ra0.z, ra0.w);            \
        Ab[(a_kp0 + 2) * AS2 + a_row] = pack2_bf16(ra1.x, ra1.y);            \
        Ab[(a_kp0 + 3) * AS2 + a_row] = pack2_bf16(ra1.z, ra1.w);            \
        Bb[(b_kp0 + 0) * BS2 + b_row] = pack2_bf16(rb0.x, rb0.y);            \
        Bb[(b_kp0 + 1) * BS2 + b_row] = pack2_bf16(rb0.z, rb0.w);            \
    } while (0)

    STAGE(0);
    __syncthreads();
    int cur = 0;

    for (int k0 = 0; k0 < Keff; k0 += 16) {
        bool nxt = (k0 + 16) < Keff;
        if (nxt) {
            ra0 = *(const float4*)(Ap + k0 + 16);
            ra1 = *(const float4*)(Ap + k0 + 20);
            rb0 = *(const float4*)(Bp + k0 + 16);
        }
        const uint2* Ab = As + cur * 8 * AS2;
        const uint2* Bb = Bs + cur * 8 * BS2;

        uint2 a[2][4];
#pragma unroll
        for (int mt = 0; mt < 2; mt++) {
            int r0 = wm + mt * 16 + gid;
            a[mt][0] = Ab[tig * AS2 + r0];
            a[mt][1] = Ab[tig * AS2 + r0 + 8];
            a[mt][2] = Ab[(tig + 4) * AS2 + r0];
            a[mt][3] = Ab[(tig + 4) * AS2 + r0 + 8];
        }
        uint2 b[4][2];
#pragma unroll
        for (int nt = 0; nt < 4; nt++) {
            int c = wn + nt * 8 + gid;
            b[nt][0] = Bb[tig * BS2 + c];
            b[nt][1] = Bb[(tig + 4) * BS2 + c];
        }
#pragma unroll
        for (int mt = 0; mt < 2; mt++) {
            uint32_t ah[4] = {a[mt][0].x, a[mt][1].x, a[mt][2].x, a[mt][3].x};
            uint32_t al[4] = {a[mt][0].y, a[mt][1].y, a[mt][2].y, a[mt][3].y};
#pragma unroll
            for (int nt = 0; nt < 4; nt++) {
                uint32_t bh[2] = {b[nt][0].x, b[nt][1].x};
                uint32_t bl[2] = {b[nt][0].y, b[nt][1].y};
                mma_bf16(acc[mt][nt], ah, bh);
                mma_bf16(acc[mt][nt], al, bh);
                mma_bf16(acc[mt][nt], ah, bl);
            }
        }
        if (nxt) {
            STAGE(cur ^ 1);
            __syncthreads();
            cur ^= 1;
        }
    }
#undef STAGE

#pragma unroll
    for (int mt = 0; mt < 2; mt++) {
        int r = i0 + wm + mt * 16 + gid;
#pragma unroll
        for (int nt = 0; nt < 4; nt++) {
            int c = j0 + wn + nt * 8 + tig * 2;
            C[(long long)r * ldc + c]           = acc[mt][nt][0];
            C[(long long)r * ldc + c + 1]       = acc[mt][nt][1];
            C[(long long)(r + 8) * ldc + c]     = acc[mt][nt][2];
            C[(long long)(r + 8) * ldc + c + 1] = acc[mt][nt][3];
        }
    }
}

// ------------------- qkv split + l2norm + kv output -------------------------
__global__ void qkv_split_kernel(const float* __restrict__ qkv,
                                 const float* __restrict__ tptr,
                                 float* __restrict__ qn, float* __restrict__ kn,
                                 float* __restrict__ vT, float* __restrict__ kv_out)
{
    int n = blockIdx.x, h = blockIdx.y, d = threadIdx.x; // 64 threads
    const float* base = qkv + (long long)n * 3072 + h * 192 + d * 3;
    float q = base[0], k = base[1], v = base[2];

    float sq = q * q, sk = k * k;
#pragma unroll
    for (int o = 16; o; o >>= 1) {
        sq += __shfl_down_sync(0xffffffffu, sq, o);
        sk += __shfl_down_sync(0xffffffffu, sk, o);
    }
    __shared__ float sh[4];
    int lane = d & 31, w = d >> 5;
    if (lane == 0) { sh[w] = sq; sh[2 + w] = sk; }
    __syncthreads();
    float nq = sqrtf(sh[0] + sh[1]);
    float nk = sqrtf(sh[2] + sh[3]);
    float temp = tptr[0];

    int idx = (h * NTOK + n) * HDIM + d;
    qn[idx] = q / fmaxf(nq, 1e-12f) * temp;
    kn[idx] = k / fmaxf(nk, 1e-12f);
    vT[(h * HDIM + d) * NTOK + n] = v;
    kv_out[idx] = k;
    kv_out[NHEAD * NTOK * HDIM + idx] = v;
}

// ---------- talking-heads pre mix + pos_bias: s = Wpre@S0 + bpre + pb -------
__global__ void __launch_bounds__(256, 3)
mix_pre_kernel(const float* __restrict__ S0,
               const float* __restrict__ Wpre,
               const float* __restrict__ bpre,
               const float* __restrict__ pb,
               float* __restrict__ s)
{
    int j0 = blockIdx.x * 64, i0 = blockIdx.y * 64;
    if (j0 > i0 + 63) return;
    __shared__ float w[16][16];
    __shared__ float bp[16];
    int t = threadIdx.x;
    w[t >> 4][t & 15] = Wpre[t];
    if (t < 16) bp[t] = bpre[t];
    __syncthreads();

    int tj = t & 63, ti = t >> 6;
    for (int r = 0; r < 16; r++) {
        int i = i0 + (r << 2) + ti;
        int j = j0 + tj;
        if (j > i) continue;
        long long cell = (long long)i * NTOK + j;
        float acc[16];
#pragma unroll
        for (int g = 0; g < 16; g++) acc[g] = bp[g];
#pragma unroll
        for (int h = 0; h < 16; h++) {
            float v = __ldg(S0 + (long long)h * NN + cell);
#pragma unroll
            for (int g = 0; g < 16; g++) acc[g] = fmaf(w[g][h], v, acc[g]);
        }
#pragma unroll
        for (int g = 0; g < 16; g++)
            s[(long long)g * NN + cell] = acc[g] + __ldg(pb + (long long)g * NN + cell);
    }
}

// ---------- per-row softmax stats (causal), single pass: m, 1/l -------------
__global__ void rowstats_kernel(const float* __restrict__ s,
                                float* __restrict__ m_out, float* __restrict__ invl_out)
{
    int i = blockIdx.x, g = blockIdx.y;
    int len = i + 1;
    const float* row = s + (long long)g * NN + (long long)i * NTOK;
    int t = threadIdx.x;

    float x[8];
#pragma unroll
    for (int b = 0; b < 2; b++) {
        int j0 = t * 4 + b * 1024;
        if (j0 + 3 < len) {
            float4 v = *(const float4*)(row + j0);
            x[b*4+0] = v.x; x[b*4+1] = v.y; x[b*4+2] = v.z; x[b*4+3] = v.w;
        } else {
#pragma unroll
            for (int u = 0; u < 4; u++) {
                int j = j0 + u;
                x[b*4+u] = (j < len) ? row[j] : -3.4e38f;
            }
        }
    }
    float m = -3.4e38f;
#pragma unroll
    for (int u = 0; u < 8; u++) m = fmaxf(m, x[u]);
    float ssum = 0.0f;
#pragma unroll
    for (int u = 0; u < 8; u++) ssum += fexp(x[u] - m);

    __shared__ float rm[256], rs[256];
    rm[t] = m; rs[t] = ssum;
    __syncthreads();
    for (int o = 128; o; o >>= 1) {
        if (t < o) {
            float m1 = rm[t], m2 = rm[t + o];
            float M = fmaxf(m1, m2);
            rs[t] = rs[t] * fexp(m1 - M) + rs[t + o] * fexp(m2 - M);
            rm[t] = M;
        }
        __syncthreads();
    }
    if (t == 0) {
        m_out[g * NTOK + i] = rm[0];
        invl_out[g * NTOK + i] = 1.0f / rs[0];
    }
}

// -------- softmax + talking-heads post: Pm = Wpost @ (exp(s-m)/l) + bpost ---
// Keeps tiles with j0 <= i0+127 (zero-filled above diagonal) so the 128-row
// PV gemm reads a rectangular K range.
__global__ void __launch_bounds__(256, 3)
softmax_mix_kernel(const float* __restrict__ s,
                   const float* __restrict__ m_arr,
                   const float* __restrict__ invl_arr,
                   const float* __restrict__ Wpost,
                   const float* __restrict__ bpost,
                   float* __restrict__ Pm)
{
    int j0 = blockIdx.x * 64, i0 = blockIdx.y * 64;
    if (j0 > i0 + 127) return;
    __shared__ float w[16][16];
    __shared__ float bp[16];
    __shared__ float sm[16][64];
    __shared__ float sil[16][64];
    int t = threadIdx.x;
    w[t >> 4][t & 15] = Wpost[t];
    if (t < 16) bp[t] = bpost[t];
#pragma unroll
    for (int e = 0; e < 4; e++) {
        int id = t + e * 256;
        int h = id >> 6, ir = id & 63;
        sm[h][ir]  = m_arr[h * NTOK + i0 + ir];
        sil[h][ir] = invl_arr[h * NTOK + i0 + ir];
    }
    __syncthreads();

    int tj = t & 63, ti = t >> 6;
    for (int r = 0; r < 16; r++) {
        int ir = (r << 2) + ti;
        int i = i0 + ir;
        int j = j0 + tj;
        long long cell = (long long)i * NTOK + j;
        if (j > i) {
#pragma unroll
            for (int g = 0; g < 16; g++) Pm[(long long)g * NN + cell] = 0.0f;
            continue;
        }
        float acc[16];
#pragma unroll
        for (int g = 0; g < 16; g++) acc[g] = bp[g];
#pragma unroll
        for (int h = 0; h < 16; h++) {
            float e = fexp(__ldg(s + (long long)h * NN + cell) - sm[h][ir]) * sil[h][ir];
#pragma unroll
            for (int g = 0; g < 16; g++) acc[g] = fmaf(w[g][h], e, acc[g]);
        }
#pragma unroll
        for (int g = 0; g < 16; g++) Pm[(long long)g * NN + cell] = acc[g];
    }
}

// ---------------------------------------------------------------------------
extern "C" void kernel_launch(void* const* d_in, const int* in_sizes, int n_in,
                              void* d_out, int out_size)
{
    const float* x     = (const float*)d_in[0];
    const float* pb    = (const float*)d_in[1];
    const float* Wqkv  = (const float*)d_in[3];
    const float* Wout  = (const float*)d_in[4];
    const float* temp  = (const float*)d_in[5];
    const float* Wpre  = (const float*)d_in[6];
    const float* bpre  = (const float*)d_in[7];
    const float* Wpost = (const float*)d_in[8];
    const float* bpost = (const float*)d_in[9];
    float* out = (float*)d_out;
    float* kv_out = out + NTOK * CDIM;

    float *qkv_p, *qn_p, *kn_p, *vT_p, *bufA_p, *bufB_p, *m_p, *invl_p, *o2_p;
    cudaGetSymbolAddress((void**)&qkv_p, g_qkv);
    cudaGetSymbolAddress((void**)&qn_p, g_qn);
    cudaGetSymbolAddress((void**)&kn_p, g_kn);
    cudaGetSymbolAddress((void**)&vT_p, g_vT);
    cudaGetSymbolAddress((void**)&bufA_p, g_bufA);
    cudaGetSymbolAddress((void**)&bufB_p, g_bufB);
    cudaGetSymbolAddress((void**)&m_p, g_m);
    cudaGetSymbolAddress((void**)&invl_p, g_invl);
    cudaGetSymbolAddress((void**)&o2_p, g_o2);

    cudaFuncSetAttribute(gemm_bf16x2, cudaFuncAttributeMaxDynamicSharedMemorySize,
                         (int)GEMM_SMEM);

    // 1) qkv = x @ Wqkv^T : [2048,3072]
    gemm_bf16x2<<<dim3(3072 / TN, 2048 / TM, 1), 256, GEMM_SMEM>>>(
        x, Wqkv, qkv_p, 1024, 1024, 1024, 3072, 0, 0, 0, 0, 0);

    // 2) split + l2norm (+temperature) + kv output + vT
    qkv_split_kernel<<<dim3(NTOK, NHEAD), 64>>>(qkv_p, temp, qn_p, kn_p, vT_p, kv_out);

    // 3) S0[h] = qn[h] @ kn[h]^T  (causal tiles only)
    gemm_bf16x2<<<dim3(2048 / TN, 2048 / TM, NHEAD), 256, GEMM_SMEM>>>(
        qn_p, kn_p, bufA_p, 64, 64, 64, 2048,
        (long long)NTOK * HDIM, (long long)NTOK * HDIM, (long long)NN, 1, 0);

    // 4) pre talking-heads mix + pos_bias -> s
    mix_pre_kernel<<<dim3(32, 32), 256>>>(bufA_p, Wpre, bpre, pb, bufB_p);

    // 5) per-row max / inv-sum-exp (single pass)
    rowstats_kernel<<<dim3(NTOK, NHEAD), 256>>>(bufB_p, m_p, invl_p);

    // 6) softmax + post talking-heads mix -> Pm (reuses bufA)
    softmax_mix_kernel<<<dim3(32, 32), 256>>>(bufB_p, m_p, invl_p, Wpost, bpost, bufA_p);

    // 7) o2 = Pm @ v (causal K limit)
    gemm_bf16x2<<<dim3(1, 2048 / TM, NHEAD), 256, GEMM_SMEM>>>(
        bufA_p, vT_p, o2_p, 2048, 2048, 2048, 1024,
        (long long)NN, (long long)HDIM * NTOK, 64, 0, 1);

    // 8) out = o2 @ Wout^T
    gemm_bf16x2<<<dim3(1024 / TN, 2048 / TM, 1), 256, GEMM_SMEM>>>(
        o2_p, Wout, out, 1024, 1024, 1024, 1024, 0, 0, 0, 0, 0);
}